// round 5
// baseline (speedup 1.0000x reference)
#include <cuda_runtime.h>

#define Bn 64
#define Cn 128
#define Ln 400
#define Hn 8
#define Kn 7
#define CLn (Cn*Ln)            // 51200
#define BCL (Bn*Cn*Ln)         // 3276800
#define EPSf 1e-5f
#define LTILE 32
#define NLT 13                 // ceil(400/32)
#define QSCALE 0.08838834764831845f

// ---------------- scratch (static device arrays; no allocation) ----------------
__device__ float g_bufA[BCL];
__device__ float g_bufB[BCL];
__device__ float g_scr[BCL];     // attention output (B,C,L)
__device__ float g_q[BCL];       // (B,H,L,DK)
__device__ float g_k[BCL];
__device__ float g_v[BCL];
__device__ float g_partA[Bn*64*2];
__device__ float g_partB[Bn*64*2];
__device__ float g_wt[9*Cn*Cn]; // transposed weights [m][c][o]: pw0..3, wq(scaled), wk, wv, wo, fc
__device__ float g_bqs[Cn];     // scaled bq
__device__ float2 g_ln2[CLn];   // (ln_g, ln_b) interleaved

// ---------------- packed f32x2 helpers ----------------
typedef unsigned long long u64;
__device__ __forceinline__ u64 pack2(float lo, float hi){
    u64 r; asm("mov.b64 %0, {%1,%2};" : "=l"(r) : "f"(lo), "f"(hi)); return r;
}
__device__ __forceinline__ void unpack2(u64 v, float& lo, float& hi){
    asm("mov.b64 {%0,%1}, %2;" : "=f"(lo), "=f"(hi) : "l"(v));
}
__device__ __forceinline__ u64 fma2(u64 a, u64 b, u64 c){
    u64 d; asm("fma.rn.f32x2 %0, %1, %2, %3;" : "=l"(d) : "l"(a), "l"(b), "l"(c)); return d;
}
__device__ __forceinline__ u64 mul2(u64 a, u64 b){
    u64 d; asm("mul.rn.f32x2 %0, %1, %2;" : "=l"(d) : "l"(a), "l"(b)); return d;
}

// deterministic 2-value block reduction, writes [sum,sumsq] to out2. red >= 2*nwarps floats
__device__ __forceinline__ void block_reduce2(float s, float ss, float* out2, float* red){
    #pragma unroll
    for (int o = 16; o > 0; o >>= 1){
        s  += __shfl_down_sync(0xffffffffu, s,  o);
        ss += __shfl_down_sync(0xffffffffu, ss, o);
    }
    int w = threadIdx.x >> 5;
    if ((threadIdx.x & 31) == 0){ red[w*2] = s; red[w*2+1] = ss; }
    __syncthreads();
    if (threadIdx.x == 0){
        float a = 0.f, b = 0.f;
        int nw = blockDim.x >> 5;
        for (int i = 0; i < nw; i++){ a += red[i*2]; b += red[i*2+1]; }
        out2[0] = a; out2[1] = b;
    }
}

// warp-0 computes mu/rsigma from partials into red[0],red[1] (needs later __syncthreads)
__device__ __forceinline__ void stats_from_parts(const float* partIn, int b, int nparts, float* red){
    if (threadIdx.x < 32){
        float s = 0.f, ss = 0.f;
        for (int i = threadIdx.x; i < nparts; i += 32){
            s  += partIn[(b*64+i)*2];
            ss += partIn[(b*64+i)*2+1];
        }
        #pragma unroll
        for (int o = 16; o > 0; o >>= 1){
            s  += __shfl_down_sync(0xffffffffu, s,  o);
            ss += __shfl_down_sync(0xffffffffu, ss, o);
        }
        if (threadIdx.x == 0){
            float mu  = s / (float)CLn;
            float var = ss / (float)CLn - mu*mu;
            red[0] = mu;
            red[1] = rsqrtf(var + EPSf);
        }
    }
}

// ---------------- prep: transpose weights + pack ln tables ----------------
__global__ __launch_bounds__(256) void k_prep(
        const float* __restrict__ pw, const float* __restrict__ wq,
        const float* __restrict__ wk, const float* __restrict__ wv,
        const float* __restrict__ wo, const float* __restrict__ fcw,
        const float* __restrict__ bq,
        const float* __restrict__ lng, const float* __restrict__ lnb){
    int idx = blockIdx.x*256 + threadIdx.x;
    if (idx < 9*Cn*Cn){
        int m = idx >> 14, r = idx & 16383;
        int o = r >> 7, c = r & 127;
        const float* src = (m < 4) ? (pw + m*Cn*Cn) :
                           (m == 4) ? wq : (m == 5) ? wk : (m == 6) ? wv :
                           (m == 7) ? wo : fcw;
        float v = src[o*Cn + c];
        if (m == 4) v *= QSCALE;
        g_wt[m*Cn*Cn + c*Cn + o] = v;
    }
    if (idx < CLn) g_ln2[idx] = make_float2(lng[idx], lnb[idx]);
    if (idx < Cn) g_bqs[idx] = bq[idx] * QSCALE;
}

// ---------------- kernel: x + positional encoding, + LN partial stats ----------------
__global__ __launch_bounds__(256) void k_pos(const float* __restrict__ x){
    __shared__ float fr[Cn], phs[Cn];
    __shared__ float red[16];
    int tid = threadIdx.x;
    if (tid < Cn){
        int c = tid;
        if ((c & 1) == 0){ fr[c] =  powf(10000.f, -(float)c/128.f);       phs[c] = 0.f; }
        else             { fr[c] = -powf(10000.f, (1.f-(float)c)/128.f);  phs[c] = 1.5707963267948966f; }
    }
    __syncthreads();
    int b  = blockIdx.x;
    int i4 = blockIdx.y * 256 + tid;                  // 0..12799
    float4 xv = ((const float4*)x)[b*(CLn/4) + i4];
    int e0 = i4 * 4;
    int c  = e0 / Ln;
    int l  = e0 - c * Ln;
    float fc = fr[c], ph = phs[c];
    float v0 = xv.x + sinf((float)(l+0)*fc + ph);
    float v1 = xv.y + sinf((float)(l+1)*fc + ph);
    float v2 = xv.z + sinf((float)(l+2)*fc + ph);
    float v3 = xv.w + sinf((float)(l+3)*fc + ph);
    ((float4*)g_bufA)[b*(CLn/4) + i4] = make_float4(v0, v1, v2, v3);
    float s  = v0 + v1 + v2 + v3;
    float ss = v0*v0 + v1*v1 + v2*v2 + v3*v3;
    block_reduce2(s, ss, &g_partA[(b*64 + blockIdx.y)*2], red);
}

// ================= GEMM mainloop v2 =====================================
// 128 threads, 4 warps. warp w: wc = w&1 selects channel half, wj = w>>1 selects 16-col group.
// lane tx: channels cb = wc*64 + 2*tx (one LDG.64, coalesced 256B/warp)
// cols: broadcast from smem, 16 per warp.
// acc[i][j]: channel cb+i, cols (wj*16 + 2j, +2j+1)
#define GEMM_CORE(WTp, XS)                                                      \
    int tx = tid & 31, w = tid >> 5;                                            \
    int wc = w & 1, wj = w >> 1;                                                \
    u64 acc[2][8];                                                              \
    _Pragma("unroll")                                                           \
    for (int i = 0; i < 2; i++){                                                \
        _Pragma("unroll")                                                       \
        for (int j = 0; j < 8; j++) acc[i][j] = 0ULL;                           \
    }                                                                           \
    {                                                                           \
        const float2* wp = (const float2*)(WTp) + wc*32 + tx;                   \
        const float*  xb = (XS) + wj*16;                                        \
        _Pragma("unroll 4")                                                     \
        for (int c = 0; c < Cn; c++){                                           \
            float2 w2 = wp[c*64];                                               \
            ulonglong2 xA = *(const ulonglong2*)(xb + c*LTILE);                 \
            ulonglong2 xB = *(const ulonglong2*)(xb + c*LTILE + 4);             \
            ulonglong2 xC = *(const ulonglong2*)(xb + c*LTILE + 8);             \
            ulonglong2 xD = *(const ulonglong2*)(xb + c*LTILE + 12);            \
            u64 W0 = pack2(w2.x, w2.x), W1 = pack2(w2.y, w2.y);                 \
            acc[0][0]=fma2(W0,xA.x,acc[0][0]); acc[0][1]=fma2(W0,xA.y,acc[0][1]); \
            acc[0][2]=fma2(W0,xB.x,acc[0][2]); acc[0][3]=fma2(W0,xB.y,acc[0][3]); \
            acc[0][4]=fma2(W0,xC.x,acc[0][4]); acc[0][5]=fma2(W0,xC.y,acc[0][5]); \
            acc[0][6]=fma2(W0,xD.x,acc[0][6]); acc[0][7]=fma2(W0,xD.y,acc[0][7]); \
            acc[1][0]=fma2(W1,xA.x,acc[1][0]); acc[1][1]=fma2(W1,xA.y,acc[1][1]); \
            acc[1][2]=fma2(W1,xB.x,acc[1][2]); acc[1][3]=fma2(W1,xB.y,acc[1][3]); \
            acc[1][4]=fma2(W1,xC.x,acc[1][4]); acc[1][5]=fma2(W1,xC.y,acc[1][5]); \
            acc[1][6]=fma2(W1,xD.x,acc[1][6]); acc[1][7]=fma2(W1,xD.y,acc[1][7]); \
        }                                                                       \
    }

// ---------------- fused conv layer ----------------
// grid (B, NLT), block 128
// smem floats: XsmH [c][38] pitch 40 = 5120 | Ysm [c][32] = 4096 | Dw 1024 | Db 128 | red 16
#define CONV_SMEM_F (5120 + 4096 + 1024 + 128 + 16)
__global__ __launch_bounds__(128, 5) void k_conv(
        const float* __restrict__ in, float* __restrict__ out,
        const float* __restrict__ Wt,
        const float* __restrict__ dw, const float* __restrict__ db,
        const float* __restrict__ pb,
        const float* __restrict__ partIn, float* __restrict__ partOut, int nparts){
    extern __shared__ float sm[];
    float* XsmH = sm;                  // [c][38] pitch 40
    float* Ysm  = sm + 5120;           // [c][32] pitch 32
    float* Dw   = Ysm + 4096;          // [c][7] pitch 8
    float* Db   = Dw + 1024;
    float* red  = Db + 128;
    int b = blockIdx.x, lt = blockIdx.y, tid = threadIdx.x;
    int l0 = lt * LTILE;

    stats_from_parts(partIn, b, nparts, red);
    for (int idx = tid; idx < Cn*Kn; idx += 128)
        Dw[(idx/7)*8 + (idx - (idx/7)*7)] = dw[idx];
    if (tid < Cn) Db[tid] = db[tid];
    __syncthreads();
    float mu = red[0], rs = red[1];
    for (int idx = tid; idx < Cn*38; idx += 128){
        int c = idx / 38, j = idx - c*38;
        int gl = l0 - 3 + j;
        float v = 0.f;
        if (gl >= 0 && gl < Ln){
            float2 gb = g_ln2[c*Ln + gl];
            float a = rs*gb.x;
            v = fmaf(in[(b*Cn + c)*Ln + gl], a, fmaf(-mu, a, gb.y));
        }
        XsmH[c*40 + j] = v;
    }
    __syncthreads();
    // depthwise: direct (separate Ysm, no aliasing)
    #pragma unroll
    for (int k = 0; k < 32; k++){
        int idx = k*128 + tid;
        int c = idx >> 5, l = idx & 31;
        float a = Db[c];
        #pragma unroll
        for (int t = 0; t < 7; t++) a += XsmH[c*40 + l + t] * Dw[c*8 + t];
        Ysm[idx] = a;
    }
    __syncthreads();

    GEMM_CORE(Wt, Ysm)

    int colBase = l0 + wj*16;
    float s = 0.f, ss = 0.f;
    if (colBase < Ln){     // 16-col group all-valid or all-invalid (400 % 16 == 0)
        int cb = wc*64 + 2*tx;
        #pragma unroll
        for (int i = 0; i < 2; i++){
            int o = cb + i;
            float bi = pb[o];
            const float* rr = &in[(b*Cn + o)*Ln + colBase];
            float* oo = &out[(b*Cn + o)*Ln + colBase];
            #pragma unroll
            for (int j = 0; j < 8; j++){
                float z0, z1; unpack2(acc[i][j], z0, z1);
                z0 += bi; z1 += bi;
                z0 = z0 > 0.f ? z0 : 0.f;  z1 = z1 > 0.f ? z1 : 0.f;
                float2 r = *(const float2*)(rr + 2*j);
                float v0 = r.x + z0, v1 = r.y + z1;
                *(float2*)(oo + 2*j) = make_float2(v0, v1);
                s += v0 + v1; ss += v0*v0 + v1*v1;
            }
        }
    }
    block_reduce2(s, ss, &partOut[(b*64 + lt)*2], red);
}

// ---------------- generic matmul: out = resid + [relu](W @ [LN](in) + bias) ----------------
// grid (B, NLT), block 128
#define MM_SMEM_F (4096 + 16)
template<bool LN, bool RELU, bool STATS>
__global__ __launch_bounds__(128, 5) void k_mm(
        const float* __restrict__ in, const float* resid, float* __restrict__ out,
        const float* __restrict__ Wt, const float* __restrict__ bias,
        const float* __restrict__ partIn, float* __restrict__ partOut, int nparts){
    extern __shared__ float sm[];
    float* Xsm = sm;                 // [c][32] pitch 32
    float* red = sm + 4096;
    int b = blockIdx.x, lt = blockIdx.y, tid = threadIdx.x;
    int l0 = lt * LTILE;
    if (LN) stats_from_parts(partIn, b, nparts, red);
    __syncthreads();
    float mu = 0.f, rs = 1.f;
    if (LN){ mu = red[0]; rs = red[1]; }
    for (int idx = tid; idx < Cn*LTILE; idx += 128){
        int c = idx >> 5, j = idx & 31;
        int gl = l0 + j;
        float v = 0.f;
        if (gl < Ln){
            v = in[(b*Cn + c)*Ln + gl];
            if (LN){
                float2 gb = g_ln2[c*Ln + gl];
                float a = rs*gb.x;
                v = fmaf(v, a, fmaf(-mu, a, gb.y));
            }
        }
        Xsm[idx] = v;
    }
    __syncthreads();

    GEMM_CORE(Wt, Xsm)

    int colBase = l0 + wj*16;
    float s = 0.f, ss = 0.f;
    if (colBase < Ln){
        int cb = wc*64 + 2*tx;
        #pragma unroll
        for (int i = 0; i < 2; i++){
            int o = cb + i;
            float bi = bias[o];
            const float* rr = &resid[(b*Cn + o)*Ln + colBase];
            float* oo = &out[(b*Cn + o)*Ln + colBase];
            #pragma unroll
            for (int j = 0; j < 8; j++){
                float z0, z1; unpack2(acc[i][j], z0, z1);
                z0 += bi; z1 += bi;
                if (RELU){ z0 = z0 > 0.f ? z0 : 0.f;  z1 = z1 > 0.f ? z1 : 0.f; }
                float2 r = *(const float2*)(rr + 2*j);
                float v0 = r.x + z0, v1 = r.y + z1;
                *(float2*)(oo + 2*j) = make_float2(v0, v1);
                if (STATS){ s += v0 + v1; ss += v0*v0 + v1*v1; }
            }
        }
    }
    if (STATS) block_reduce2(s, ss, &partOut[(b*64 + lt)*2], red);
}

// ---------------- QKV projections (LN on input), writes (B,H,L,DK) ----------------
// grid (B, NLT, 3), block 128
__global__ __launch_bounds__(128, 5) void k_qkv(
        const float* __restrict__ in,
        const float* __restrict__ bq_s, const float* __restrict__ bk,
        const float* __restrict__ bv,
        const float* __restrict__ partIn, int nparts){
    extern __shared__ float sm[];
    float* Xsm = sm;
    float* red = sm + 4096;
    int which = blockIdx.z;
    const float* Wt   = g_wt + (4 + which)*Cn*Cn;
    const float* bias = which == 0 ? bq_s : (which == 1 ? bk : bv);
    float* outp       = which == 0 ? g_q : (which == 1 ? g_k : g_v);
    int b = blockIdx.x, lt = blockIdx.y, tid = threadIdx.x;
    int l0 = lt * LTILE;
    stats_from_parts(partIn, b, nparts, red);
    __syncthreads();
    float mu = red[0], rs = red[1];
    for (int idx = tid; idx < Cn*LTILE; idx += 128){
        int c = idx >> 5, j = idx & 31;
        int gl = l0 + j;
        float v = 0.f;
        if (gl < Ln){
            float2 gb = g_ln2[c*Ln + gl];
            float a = rs*gb.x;
            v = fmaf(in[(b*Cn + c)*Ln + gl], a, fmaf(-mu, a, gb.y));
        }
        Xsm[idx] = v;
    }
    __syncthreads();

    GEMM_CORE(Wt, Xsm)

    int colBase = l0 + wj*16;
    if (colBase < Ln){
        int cb = wc*64 + 2*tx;          // 2 consecutive out-channels
        int h  = cb >> 4;               // head
        int d  = cb & 15;               // dim within head (even)
        float b0 = bias[cb], b1 = bias[cb+1];
        float* basep = outp + ((size_t)(b*Hn + h)*Ln + colBase)*16 + d;
        #pragma unroll
        for (int j = 0; j < 8; j++){
            float z0, z1; unpack2(acc[0][j], z0, z1);
            float y0, y1; unpack2(acc[1][j], y0, y1);
            float* p = basep + (2*j)*16;
            *(float2*)p        = make_float2(z0 + b0, y0 + b1);
            *(float2*)(p + 16) = make_float2(z1 + b0, y1 + b1);
        }
    }
}

// ---------------- attention: per (b,h), online softmax, 2 rows/thread ----------------
// grid (B*H), block 224 ; thread t handles rows t and t+200 (t<200)
#define ATTN_SMEM_F (Ln*16 + Ln*16 + Ln)
__global__ __launch_bounds__(224) void k_attn(const float* __restrict__ mask){
    extern __shared__ float sm[];
    float* Ksm = sm;
    float* Vsm = Ksm + Ln*16;
    float* Msm = Vsm + Ln*16;
    int bh = blockIdx.x;
    int b = bh >> 3, h = bh & 7;
    int tid = threadIdx.x;
    const float4* kp = (const float4*)(g_k + (size_t)bh*Ln*16);
    const float4* vp = (const float4*)(g_v + (size_t)bh*Ln*16);
    for (int i = tid; i < Ln*4; i += 224){
        ((float4*)Ksm)[i] = kp[i];
        ((float4*)Vsm)[i] = vp[i];
    }
    for (int i = tid; i < Ln; i += 224) Msm[i] = mask[b*Ln + i];
    __syncthreads();

    if (tid >= 200) return;
    int r0 = tid, r1 = tid + 200;
    u64 q0[8], q1[8];
    {
        const u64* qp0 = (const u64*)(g_q + ((size_t)bh*Ln + r0)*16);
        const u64* qp1 = (const u64*)(g_q + ((size_t)bh*Ln + r1)*16);
        #pragma unroll
        for (int i = 0; i < 8; i++){ q0[i] = qp0[i]; q1[i] = qp1[i]; }
    }

    float m0 = -3.0e38f, m1 = -3.0e38f, den0 = 0.f, den1 = 0.f;
    u64 a0[8], a1[8];
    #pragma unroll
    for (int i = 0; i < 8; i++){ a0[i] = 0ULL; a1[i] = 0ULL; }

    for (int j = 0; j < Ln; j++){
        const ulonglong2* kr = (const ulonglong2*)(Ksm + j*16);
        ulonglong2 ka = kr[0], kb = kr[1], kc = kr[2], kd = kr[3];
        u64 s2;
        s2 = mul2(q0[0], ka.x);      s2 = fma2(q0[1], ka.y, s2);
        s2 = fma2(q0[2], kb.x, s2);  s2 = fma2(q0[3], kb.y, s2);
        s2 = fma2(q0[4], kc.x, s2);  s2 = fma2(q0[5], kc.y, s2);
        s2 = fma2(q0[6], kd.x, s2);  s2 = fma2(q0[7], kd.y, s2);
        float lo, hi; unpack2(s2, lo, hi);
        float sc0 = lo + hi;
        s2 = mul2(q1[0], ka.x);      s2 = fma2(q1[1], ka.y, s2);
        s2 = fma2(q1[2], kb.x, s2);  s2 = fma2(q1[3], kb.y, s2);
        s2 = fma2(q1[4], kc.x, s2);  s2 = fma2(q1[5], kc.y, s2);
        s2 = fma2(q1[6], kd.x, s2);  s2 = fma2(q1[7], kd.y, s2);
        unpack2(s2, lo, hi);
        float sc1 = lo + hi;

        float mk  = Msm[j];
        float adj = (1.f - mk)*(-1e30f);
        sc0 = sc0*mk + adj;
        sc1 = sc1*mk + adj;

        const ulonglong2* vr = (const ulonglong2*)(Vsm + j*16);
        ulonglong2 va = vr[0], vb = vr[1], vc = vr[2], vd = vr[3];

        if (sc0 > m0){
            float f = __expf(m0 - sc0);
            u64 f2 = pack2(f, f);
            #pragma unroll
            for (int i = 0; i < 8; i++) a0[i] = mul2(a0[i], f2);
            den0 *= f; m0 = sc0;
        }
        float p0 = __expf(sc0 - m0);
        den0 += p0;
        u64 p02 = pack2(p0, p0);
        a0[0] = fma2(va.x, p02, a0[0]); a0[1] = fma2(va.y, p02, a0[1]);
        a0[2] = fma2(vb.x, p02, a0[2]); a0[3] = fma2(vb.y, p02, a0[3]);
        a0[4] = fma2(vc.x, p02, a0[4]); a0[5] = fma2(vc.y, p02, a0[5]);
        a0[6] = fma2(vd.x, p02, a0[6]); a0[7] = fma2(vd.y, p02, a0[7]);

        if (sc1 > m1){
            float f = __expf(m1 - sc1);
            u64 f2 = pack2(f, f);
            #pragma unroll
            for (int i = 0; i < 8; i++) a1[i] = mul2(a1[i], f2);
            den1 *= f; m1 = sc1;
        }
        float p1 = __expf(sc1 - m1);
        den1 += p1;
        u64 p12 = pack2(p1, p1);
        a1[0] = fma2(va.x, p12, a1[0]); a1[1] = fma2(va.y, p12, a1[1]);
        a1[2] = fma2(vb.x, p12, a1[2]); a1[3] = fma2(vb.y, p12, a1[3]);
        a1[4] = fma2(vc.x, p12, a1[4]); a1[5] = fma2(vc.y, p12, a1[5]);
        a1[6] = fma2(vd.x, p12, a1[6]); a1[7] = fma2(vd.y, p12, a1[7]);
    }

    size_t base = ((size_t)b*Cn + h*16)*Ln;
    float inv0 = 1.f/den0, inv1 = 1.f/den1;
    #pragma unroll
    for (int i = 0; i < 8; i++){
        float z0, z1, y0, y1;
        unpack2(a0[i], z0, z1);
        unpack2(a1[i], y0, y1);
        g_scr[base + (size_t)(2*i  )*Ln + r0] = z0*inv0;
        g_scr[base + (size_t)(2*i+1)*Ln + r0] = z1*inv0;
        g_scr[base + (size_t)(2*i  )*Ln + r1] = y0*inv1;
        g_scr[base + (size_t)(2*i+1)*Ln + r1] = y1*inv1;
    }
}

// ---------------- host launcher ----------------
extern "C" void kernel_launch(void* const* d_in, const int* in_sizes, int n_in,
                              void* d_out, int out_size){
    (void)in_sizes; (void)n_in; (void)out_size;
    const float* x    = (const float*)d_in[0];
    const float* mask = (const float*)d_in[1];
    const float* dw_w = (const float*)d_in[2];
    const float* dw_b = (const float*)d_in[3];
    const float* pw_w = (const float*)d_in[4];
    const float* pw_b = (const float*)d_in[5];
    const float* wq   = (const float*)d_in[6];
    const float* bq   = (const float*)d_in[7];
    const float* wk   = (const float*)d_in[8];
    const float* bk   = (const float*)d_in[9];
    const float* wv   = (const float*)d_in[10];
    const float* bv   = (const float*)d_in[11];
    const float* wo   = (const float*)d_in[12];
    const float* bo   = (const float*)d_in[13];
    const float* fc_w = (const float*)d_in[14];
    const float* fc_b = (const float*)d_in[15];
    const float* ln_g = (const float*)d_in[16];
    const float* ln_b = (const float*)d_in[17];
    float* outp = (float*)d_out;

    float *bufA, *bufB, *scr, *pA, *pB, *wt, *bqs;
    cudaGetSymbolAddress((void**)&bufA, g_bufA);
    cudaGetSymbolAddress((void**)&bufB, g_bufB);
    cudaGetSymbolAddress((void**)&scr,  g_scr);
    cudaGetSymbolAddress((void**)&pA,   g_partA);
    cudaGetSymbolAddress((void**)&pB,   g_partB);
    cudaGetSymbolAddress((void**)&wt,   g_wt);
    cudaGetSymbolAddress((void**)&bqs,  g_bqs);

    const int CONV_SMEM = CONV_SMEM_F * 4;
    const int MM_SMEM   = MM_SMEM_F * 4;
    const int ATTN_SMEM = ATTN_SMEM_F * 4;
    cudaFuncSetAttribute(k_attn, cudaFuncAttributeMaxDynamicSharedMemorySize, ATTN_SMEM);

    // stage 0: weight transposes + ln pack
    k_prep<<<(9*Cn*Cn + 255)/256, 256>>>(pw_w, wq, wk, wv, wo, fc_w, bq, ln_g, ln_b);

    // stage 1: x + pos, LN partials -> pA
    k_pos<<<dim3(Bn, 50), 256>>>(x);

    // stage 2: 4 fused conv layers (ping-pong buffers AND ping-pong partials)
    float* cin  = bufA;
    float* cout = bufB;
    const float* pin = pA;
    float* pout = pB;
    int nparts = 50;
    for (int i = 0; i < 4; i++){
        k_conv<<<dim3(Bn, NLT), 128, CONV_SMEM>>>(cin, cout,
            wt + i*Cn*Cn, dw_w + i*Cn*Kn, dw_b + i*Cn, pw_b + i*Cn,
            pin, pout, nparts);
        float* t = cin; cin = cout; cout = t;
        float* tp = (float*)pin; pin = pout; pout = tp;
        nparts = NLT;
    }
    // cin = residual after 4 conv layers; stats partials in pin (nparts=13)

    // stage 3: attention
    k_qkv<<<dim3(Bn, NLT, 3), 128, MM_SMEM>>>(cin, bqs, bk, bv, pin, nparts);
    k_attn<<<Bn*Hn, 224, ATTN_SMEM>>>(mask);
    // o-proj: out = resid + W@scr ; stats -> pout
    k_mm<false,false,true><<<dim3(Bn, NLT), 128, MM_SMEM>>>(scr, cin, cout,
        wt + 7*Cn*Cn, bo, nullptr, pout, 0);

    // stage 4: FC + relu + residual -> final output (stats from pout)
    k_mm<true,true,false><<<dim3(Bn, NLT), 128, MM_SMEM>>>(cout, cout, outp,
        wt + 8*Cn*Cn, fc_b, pout, nullptr, NLT);
}

// round 6
// speedup vs baseline: 1.1005x; 1.1005x over previous
#include <cuda_runtime.h>

#define Bn 64
#define Cn 128
#define Ln 400
#define Hn 8
#define Kn 7
#define CLn (Cn*Ln)            // 51200
#define BCL (Bn*Cn*Ln)         // 3276800
#define EPSf 1e-5f
#define LTILE 64
#define NLT 7                  // ceil(400/64)
#define QSCALE 0.08838834764831845f

// ---------------- scratch (static device arrays; no allocation) ----------------
__device__ float g_bufA[BCL];
__device__ float g_bufB[BCL];
__device__ float g_scr[BCL];     // attention output (B,C,L)
__device__ float g_q[BCL];       // (B,H,L,DK)
__device__ float g_k[BCL];
__device__ float g_v[BCL];
__device__ float g_partA[Bn*64*2];
__device__ float g_partB[Bn*64*2];
__device__ float g_wt[9*Cn*Cn]; // transposed weights [m][c][o]: pw0..3, wq(scaled), wk, wv, wo, fc
__device__ float g_bqs[Cn];     // scaled bq
__device__ float2 g_ln2[CLn];   // (ln_g, ln_b) interleaved

// ---------------- packed f32x2 helpers ----------------
typedef unsigned long long u64;
__device__ __forceinline__ u64 pack2(float lo, float hi){
    u64 r; asm("mov.b64 %0, {%1,%2};" : "=l"(r) : "f"(lo), "f"(hi)); return r;
}
__device__ __forceinline__ void unpack2(u64 v, float& lo, float& hi){
    asm("mov.b64 {%0,%1}, %2;" : "=f"(lo), "=f"(hi) : "l"(v));
}
__device__ __forceinline__ u64 fma2(u64 a, u64 b, u64 c){
    u64 d; asm("fma.rn.f32x2 %0, %1, %2, %3;" : "=l"(d) : "l"(a), "l"(b), "l"(c)); return d;
}
__device__ __forceinline__ u64 mul2(u64 a, u64 b){
    u64 d; asm("mul.rn.f32x2 %0, %1, %2;" : "=l"(d) : "l"(a), "l"(b)); return d;
}

// deterministic 2-value block reduction, writes [sum,sumsq] to out2. red >= 2*nwarps floats
__device__ __forceinline__ void block_reduce2(float s, float ss, float* out2, float* red){
    #pragma unroll
    for (int o = 16; o > 0; o >>= 1){
        s  += __shfl_down_sync(0xffffffffu, s,  o);
        ss += __shfl_down_sync(0xffffffffu, ss, o);
    }
    int w = threadIdx.x >> 5;
    if ((threadIdx.x & 31) == 0){ red[w*2] = s; red[w*2+1] = ss; }
    __syncthreads();
    if (threadIdx.x == 0){
        float a = 0.f, b = 0.f;
        int nw = blockDim.x >> 5;
        for (int i = 0; i < nw; i++){ a += red[i*2]; b += red[i*2+1]; }
        out2[0] = a; out2[1] = b;
    }
}

// warp-0 computes mu/rsigma from partials into red[0],red[1] (needs later __syncthreads)
__device__ __forceinline__ void stats_from_parts(const float* partIn, int b, int nparts, float* red){
    if (threadIdx.x < 32){
        float s = 0.f, ss = 0.f;
        for (int i = threadIdx.x; i < nparts; i += 32){
            s  += partIn[(b*64+i)*2];
            ss += partIn[(b*64+i)*2+1];
        }
        #pragma unroll
        for (int o = 16; o > 0; o >>= 1){
            s  += __shfl_down_sync(0xffffffffu, s,  o);
            ss += __shfl_down_sync(0xffffffffu, ss, o);
        }
        if (threadIdx.x == 0){
            float mu  = s / (float)CLn;
            float var = ss / (float)CLn - mu*mu;
            red[0] = mu;
            red[1] = rsqrtf(var + EPSf);
        }
    }
}

// ---------------- prep: transpose weights + pack ln tables ----------------
__global__ __launch_bounds__(256) void k_prep(
        const float* __restrict__ pw, const float* __restrict__ wq,
        const float* __restrict__ wk, const float* __restrict__ wv,
        const float* __restrict__ wo, const float* __restrict__ fcw,
        const float* __restrict__ bq,
        const float* __restrict__ lng, const float* __restrict__ lnb){
    int idx = blockIdx.x*256 + threadIdx.x;
    if (idx < 9*Cn*Cn){
        int m = idx >> 14, r = idx & 16383;
        int o = r >> 7, c = r & 127;
        const float* src = (m < 4) ? (pw + m*Cn*Cn) :
                           (m == 4) ? wq : (m == 5) ? wk : (m == 6) ? wv :
                           (m == 7) ? wo : fcw;
        float v = src[o*Cn + c];
        if (m == 4) v *= QSCALE;
        g_wt[m*Cn*Cn + c*Cn + o] = v;
    }
    if (idx < CLn) g_ln2[idx] = make_float2(lng[idx], lnb[idx]);
    if (idx < Cn) g_bqs[idx] = bq[idx] * QSCALE;
}

// ---------------- kernel: x + positional encoding, + LN partial stats ----------------
__global__ __launch_bounds__(256) void k_pos(const float* __restrict__ x){
    __shared__ float fr[Cn], phs[Cn];
    __shared__ float red[16];
    int tid = threadIdx.x;
    if (tid < Cn){
        int c = tid;
        if ((c & 1) == 0){ fr[c] =  powf(10000.f, -(float)c/128.f);       phs[c] = 0.f; }
        else             { fr[c] = -powf(10000.f, (1.f-(float)c)/128.f);  phs[c] = 1.5707963267948966f; }
    }
    __syncthreads();
    int b  = blockIdx.x;
    int i4 = blockIdx.y * 256 + tid;                  // 0..12799
    float4 xv = ((const float4*)x)[b*(CLn/4) + i4];
    int e0 = i4 * 4;
    int c  = e0 / Ln;
    int l  = e0 - c * Ln;
    float fc = fr[c], ph = phs[c];
    float v0 = xv.x + sinf((float)(l+0)*fc + ph);
    float v1 = xv.y + sinf((float)(l+1)*fc + ph);
    float v2 = xv.z + sinf((float)(l+2)*fc + ph);
    float v3 = xv.w + sinf((float)(l+3)*fc + ph);
    ((float4*)g_bufA)[b*(CLn/4) + i4] = make_float4(v0, v1, v2, v3);
    float s  = v0 + v1 + v2 + v3;
    float ss = v0*v0 + v1*v1 + v2*v2 + v3*v3;
    block_reduce2(s, ss, &g_partA[(b*64 + blockIdx.y)*2], red);
}

// ================= GEMM mainloop v3 =====================================
// 128 threads, 4 warps. warp w: cols 16w..16w+15 ; lane tx: out-channels 4tx..4tx+3
// acc[i][j]: channel 4tx+i, cols (16w+2j, 16w+2j+1), j=0..7
#define GEMM_CORE(WTp, XS, XPITCH)                                              \
    int tx = tid & 31, w = tid >> 5;                                            \
    u64 acc[4][8];                                                              \
    _Pragma("unroll")                                                           \
    for (int i = 0; i < 4; i++){                                                \
        _Pragma("unroll")                                                       \
        for (int j = 0; j < 8; j++) acc[i][j] = 0ULL;                           \
    }                                                                           \
    {                                                                           \
        const float4* wp = ((const float4*)(WTp)) + tx;                         \
        const float*  xb = (XS) + 16*w;                                         \
        _Pragma("unroll 4")                                                     \
        for (int c = 0; c < Cn; c++){                                           \
            float4 w4 = wp[c*32];                                               \
            ulonglong2 xA = *(const ulonglong2*)(xb + c*(XPITCH));              \
            ulonglong2 xB = *(const ulonglong2*)(xb + c*(XPITCH) + 4);          \
            ulonglong2 xC = *(const ulonglong2*)(xb + c*(XPITCH) + 8);          \
            ulonglong2 xD = *(const ulonglong2*)(xb + c*(XPITCH) + 12);         \
            u64 W0 = pack2(w4.x, w4.x), W1 = pack2(w4.y, w4.y);                 \
            u64 W2 = pack2(w4.z, w4.z), W3 = pack2(w4.w, w4.w);                 \
            acc[0][0]=fma2(W0,xA.x,acc[0][0]); acc[0][1]=fma2(W0,xA.y,acc[0][1]); \
            acc[0][2]=fma2(W0,xB.x,acc[0][2]); acc[0][3]=fma2(W0,xB.y,acc[0][3]); \
            acc[0][4]=fma2(W0,xC.x,acc[0][4]); acc[0][5]=fma2(W0,xC.y,acc[0][5]); \
            acc[0][6]=fma2(W0,xD.x,acc[0][6]); acc[0][7]=fma2(W0,xD.y,acc[0][7]); \
            acc[1][0]=fma2(W1,xA.x,acc[1][0]); acc[1][1]=fma2(W1,xA.y,acc[1][1]); \
            acc[1][2]=fma2(W1,xB.x,acc[1][2]); acc[1][3]=fma2(W1,xB.y,acc[1][3]); \
            acc[1][4]=fma2(W1,xC.x,acc[1][4]); acc[1][5]=fma2(W1,xC.y,acc[1][5]); \
            acc[1][6]=fma2(W1,xD.x,acc[1][6]); acc[1][7]=fma2(W1,xD.y,acc[1][7]); \
            acc[2][0]=fma2(W2,xA.x,acc[2][0]); acc[2][1]=fma2(W2,xA.y,acc[2][1]); \
            acc[2][2]=fma2(W2,xB.x,acc[2][2]); acc[2][3]=fma2(W2,xB.y,acc[2][3]); \
            acc[2][4]=fma2(W2,xC.x,acc[2][4]); acc[2][5]=fma2(W2,xC.y,acc[2][5]); \
            acc[2][6]=fma2(W2,xD.x,acc[2][6]); acc[2][7]=fma2(W2,xD.y,acc[2][7]); \
            acc[3][0]=fma2(W3,xA.x,acc[3][0]); acc[3][1]=fma2(W3,xA.y,acc[3][1]); \
            acc[3][2]=fma2(W3,xB.x,acc[3][2]); acc[3][3]=fma2(W3,xB.y,acc[3][3]); \
            acc[3][4]=fma2(W3,xC.x,acc[3][4]); acc[3][5]=fma2(W3,xC.y,acc[3][5]); \
            acc[3][6]=fma2(W3,xD.x,acc[3][6]); acc[3][7]=fma2(W3,xD.y,acc[3][7]); \
        }                                                                       \
    }

// ---------------- fused conv layer ----------------
// grid (B, NLT), block 128
// smem floats: XsmH [c][70] pitch 72 = 9216 | Ysm [c][64] = 8192 | Dw 1024 | Db 128 | red 16
#define CONV_SMEM_F (9216 + 8192 + 1024 + 128 + 16)
__global__ __launch_bounds__(128, 3) void k_conv(
        const float* __restrict__ in, float* __restrict__ out,
        const float* __restrict__ Wt,
        const float* __restrict__ dw, const float* __restrict__ db,
        const float* __restrict__ pb,
        const float* __restrict__ partIn, float* __restrict__ partOut, int nparts){
    extern __shared__ float sm[];
    float* XsmH = sm;                  // [c][70] pitch 72
    float* Ysm  = sm + 9216;           // [c][64] pitch 64
    float* Dw   = Ysm + 8192;          // [c][7] pitch 8
    float* Db   = Dw + 1024;
    float* red  = Db + 128;
    int b = blockIdx.x, lt = blockIdx.y, tid = threadIdx.x;
    int l0 = lt * LTILE;

    stats_from_parts(partIn, b, nparts, red);
    for (int idx = tid; idx < Cn*Kn; idx += 128)
        Dw[(idx/7)*8 + (idx - (idx/7)*7)] = dw[idx];
    if (tid < Cn) Db[tid] = db[tid];
    __syncthreads();
    float mu = red[0], rs = red[1];
    for (int idx = tid; idx < Cn*70; idx += 128){
        int c = idx / 70, j = idx - c*70;
        int gl = l0 - 3 + j;
        float v = 0.f;
        if (gl >= 0 && gl < Ln){
            float2 gb = g_ln2[c*Ln + gl];
            float a = rs*gb.x;
            v = fmaf(in[(b*Cn + c)*Ln + gl], a, fmaf(-mu, a, gb.y));
        }
        XsmH[c*72 + j] = v;
    }
    __syncthreads();
    // depthwise: warp-row mapping, coalesced LDS/STS
    #pragma unroll
    for (int k = 0; k < 64; k++){
        int idx = k*128 + tid;
        int c = idx >> 6, l = idx & 63;
        float a = Db[c];
        #pragma unroll
        for (int t = 0; t < 7; t++) a += XsmH[c*72 + l + t] * Dw[c*8 + t];
        Ysm[idx] = a;
    }
    __syncthreads();

    GEMM_CORE(Wt, Ysm, 64)

    int colBase = l0 + 16*w;
    float s = 0.f, ss = 0.f;
    if (colBase < Ln){     // 16-col group all-valid or all-invalid (400 % 16 == 0)
        float4 b4 = *(const float4*)&pb[4*tx];
        float bias[4] = {b4.x, b4.y, b4.z, b4.w};
        #pragma unroll
        for (int i = 0; i < 4; i++){
            int o = 4*tx + i;
            const float* rr = &in[(b*Cn + o)*Ln + colBase];
            float* oo = &out[(b*Cn + o)*Ln + colBase];
            #pragma unroll
            for (int j = 0; j < 8; j++){
                float z0, z1; unpack2(acc[i][j], z0, z1);
                z0 += bias[i]; z1 += bias[i];
                z0 = z0 > 0.f ? z0 : 0.f;  z1 = z1 > 0.f ? z1 : 0.f;
                float2 r = *(const float2*)(rr + 2*j);
                float v0 = r.x + z0, v1 = r.y + z1;
                *(float2*)(oo + 2*j) = make_float2(v0, v1);
                s += v0 + v1; ss += v0*v0 + v1*v1;
            }
        }
    }
    block_reduce2(s, ss, &partOut[(b*64 + lt)*2], red);
}

// ---------------- generic matmul: out = resid + [relu](W @ [LN](in) + bias) ----------------
// grid (B, NLT), block 128
#define MM_SMEM_F (8192 + 16)
template<bool LN, bool RELU, bool STATS>
__global__ __launch_bounds__(128, 4) void k_mm(
        const float* __restrict__ in, const float* resid, float* __restrict__ out,
        const float* __restrict__ Wt, const float* __restrict__ bias,
        const float* __restrict__ partIn, float* __restrict__ partOut, int nparts){
    extern __shared__ float sm[];
    float* Xsm = sm;                 // [c][64] pitch 64
    float* red = sm + 8192;
    int b = blockIdx.x, lt = blockIdx.y, tid = threadIdx.x;
    int l0 = lt * LTILE;
    if (LN) stats_from_parts(partIn, b, nparts, red);
    __syncthreads();
    float mu = 0.f, rs = 1.f;
    if (LN){ mu = red[0]; rs = red[1]; }
    for (int idx = tid; idx < Cn*LTILE; idx += 128){
        int c = idx >> 6, j = idx & 63;
        int gl = l0 + j;
        float v = 0.f;
        if (gl < Ln){
            v = in[(b*Cn + c)*Ln + gl];
            if (LN){
                float2 gb = g_ln2[c*Ln + gl];
                float a = rs*gb.x;
                v = fmaf(v, a, fmaf(-mu, a, gb.y));
            }
        }
        Xsm[idx] = v;
    }
    __syncthreads();

    GEMM_CORE(Wt, Xsm, 64)

    int colBase = l0 + 16*w;
    float s = 0.f, ss = 0.f;
    if (colBase < Ln){
        float4 b4 = *(const float4*)&bias[4*tx];
        float bi[4] = {b4.x, b4.y, b4.z, b4.w};
        #pragma unroll
        for (int i = 0; i < 4; i++){
            int o = 4*tx + i;
            const float* rr = &resid[(b*Cn + o)*Ln + colBase];
            float* oo = &out[(b*Cn + o)*Ln + colBase];
            #pragma unroll
            for (int j = 0; j < 8; j++){
                float z0, z1; unpack2(acc[i][j], z0, z1);
                z0 += bi[i]; z1 += bi[i];
                if (RELU){ z0 = z0 > 0.f ? z0 : 0.f;  z1 = z1 > 0.f ? z1 : 0.f; }
                float2 r = *(const float2*)(rr + 2*j);
                float v0 = r.x + z0, v1 = r.y + z1;
                *(float2*)(oo + 2*j) = make_float2(v0, v1);
                if (STATS){ s += v0 + v1; ss += v0*v0 + v1*v1; }
            }
        }
    }
    if (STATS) block_reduce2(s, ss, &partOut[(b*64 + lt)*2], red);
}

// ---------------- QKV projections (LN on input), writes (B,H,L,DK) ----------------
// grid (B, NLT, 3), block 128
__global__ __launch_bounds__(128, 4) void k_qkv(
        const float* __restrict__ in,
        const float* __restrict__ bq_s, const float* __restrict__ bk,
        const float* __restrict__ bv,
        const float* __restrict__ partIn, int nparts){
    extern __shared__ float sm[];
    float* Xsm = sm;
    float* red = sm + 8192;
    int which = blockIdx.z;
    const float* Wt   = g_wt + (4 + which)*Cn*Cn;
    const float* bias = which == 0 ? bq_s : (which == 1 ? bk : bv);
    float* outp       = which == 0 ? g_q : (which == 1 ? g_k : g_v);
    int b = blockIdx.x, lt = blockIdx.y, tid = threadIdx.x;
    int l0 = lt * LTILE;
    stats_from_parts(partIn, b, nparts, red);
    __syncthreads();
    float mu = red[0], rs = red[1];
    for (int idx = tid; idx < Cn*LTILE; idx += 128){
        int c = idx >> 6, j = idx & 63;
        int gl = l0 + j;
        float v = 0.f;
        if (gl < Ln){
            float2 gb = g_ln2[c*Ln + gl];
            float a = rs*gb.x;
            v = fmaf(in[(b*Cn + c)*Ln + gl], a, fmaf(-mu, a, gb.y));
        }
        Xsm[idx] = v;
    }
    __syncthreads();

    GEMM_CORE(Wt, Xsm, 64)

    int colBase = l0 + 16*w;
    if (colBase < Ln){
        float4 b4 = *(const float4*)&bias[4*tx];
        int cb = 4*tx;                  // 4 consecutive out-channels
        int h  = tx >> 2;               // head
        int d  = (tx & 3) * 4;          // dim within head
        float* basep = outp + ((size_t)(b*Hn + h)*Ln + colBase)*16 + d;
        #pragma unroll
        for (int j = 0; j < 8; j++){
            float z0lo, z0hi, z1lo, z1hi, z2lo, z2hi, z3lo, z3hi;
            unpack2(acc[0][j], z0lo, z0hi);
            unpack2(acc[1][j], z1lo, z1hi);
            unpack2(acc[2][j], z2lo, z2hi);
            unpack2(acc[3][j], z3lo, z3hi);
            float* p = basep + (2*j)*16;
            *(float4*)p        = make_float4(z0lo + b4.x, z1lo + b4.y, z2lo + b4.z, z3lo + b4.w);
            *(float4*)(p + 16) = make_float4(z0hi + b4.x, z1hi + b4.y, z2hi + b4.z, z3hi + b4.w);
        }
        (void)cb;
    }
}

// ---------------- attention: per (b,h), online softmax, 2 rows/thread ----------------
// grid (B*H), block 224 ; thread t handles rows t and t+200 (t<200)
#define ATTN_SMEM_F (Ln*16 + Ln*16 + Ln)
__global__ __launch_bounds__(224) void k_attn(const float* __restrict__ mask){
    extern __shared__ float sm[];
    float* Ksm = sm;
    float* Vsm = Ksm + Ln*16;
    float* Msm = Vsm + Ln*16;
    int bh = blockIdx.x;
    int b = bh >> 3, h = bh & 7;
    int tid = threadIdx.x;
    const float4* kp = (const float4*)(g_k + (size_t)bh*Ln*16);
    const float4* vp = (const float4*)(g_v + (size_t)bh*Ln*16);
    for (int i = tid; i < Ln*4; i += 224){
        ((float4*)Ksm)[i] = kp[i];
        ((float4*)Vsm)[i] = vp[i];
    }
    for (int i = tid; i < Ln; i += 224) Msm[i] = mask[b*Ln + i];
    __syncthreads();

    if (tid >= 200) return;
    int r0 = tid, r1 = tid + 200;
    u64 q0[8], q1[8];
    {
        const u64* qp0 = (const u64*)(g_q + ((size_t)bh*Ln + r0)*16);
        const u64* qp1 = (const u64*)(g_q + ((size_t)bh*Ln + r1)*16);
        #pragma unroll
        for (int i = 0; i < 8; i++){ q0[i] = qp0[i]; q1[i] = qp1[i]; }
    }

    float m0 = -3.0e38f, m1 = -3.0e38f, den0 = 0.f, den1 = 0.f;
    u64 a0[8], a1[8];
    #pragma unroll
    for (int i = 0; i < 8; i++){ a0[i] = 0ULL; a1[i] = 0ULL; }

    for (int j = 0; j < Ln; j++){
        const ulonglong2* kr = (const ulonglong2*)(Ksm + j*16);
        ulonglong2 ka = kr[0], kb = kr[1], kc = kr[2], kd = kr[3];
        u64 s2;
        s2 = mul2(q0[0], ka.x);      s2 = fma2(q0[1], ka.y, s2);
        s2 = fma2(q0[2], kb.x, s2);  s2 = fma2(q0[3], kb.y, s2);
        s2 = fma2(q0[4], kc.x, s2);  s2 = fma2(q0[5], kc.y, s2);
        s2 = fma2(q0[6], kd.x, s2);  s2 = fma2(q0[7], kd.y, s2);
        float lo, hi; unpack2(s2, lo, hi);
        float sc0 = lo + hi;
        s2 = mul2(q1[0], ka.x);      s2 = fma2(q1[1], ka.y, s2);
        s2 = fma2(q1[2], kb.x, s2);  s2 = fma2(q1[3], kb.y, s2);
        s2 = fma2(q1[4], kc.x, s2);  s2 = fma2(q1[5], kc.y, s2);
        s2 = fma2(q1[6], kd.x, s2);  s2 = fma2(q1[7], kd.y, s2);
        unpack2(s2, lo, hi);
        float sc1 = lo + hi;

        float mk  = Msm[j];
        float adj = (1.f - mk)*(-1e30f);
        sc0 = sc0*mk + adj;
        sc1 = sc1*mk + adj;

        const ulonglong2* vr = (const ulonglong2*)(Vsm + j*16);
        ulonglong2 va = vr[0], vb = vr[1], vc = vr[2], vd = vr[3];

        if (sc0 > m0){
            float f = __expf(m0 - sc0);
            u64 f2 = pack2(f, f);
            #pragma unroll
            for (int i = 0; i < 8; i++) a0[i] = mul2(a0[i], f2);
            den0 *= f; m0 = sc0;
        }
        float p0 = __expf(sc0 - m0);
        den0 += p0;
        u64 p02 = pack2(p0, p0);
        a0[0] = fma2(va.x, p02, a0[0]); a0[1] = fma2(va.y, p02, a0[1]);
        a0[2] = fma2(vb.x, p02, a0[2]); a0[3] = fma2(vb.y, p02, a0[3]);
        a0[4] = fma2(vc.x, p02, a0[4]); a0[5] = fma2(vc.y, p02, a0[5]);
        a0[6] = fma2(vd.x, p02, a0[6]); a0[7] = fma2(vd.y, p02, a0[7]);

        if (sc1 > m1){
            float f = __expf(m1 - sc1);
            u64 f2 = pack2(f, f);
            #pragma unroll
            for (int i = 0; i < 8; i++) a1[i] = mul2(a1[i], f2);
            den1 *= f; m1 = sc1;
        }
        float p1 = __expf(sc1 - m1);
        den1 += p1;
        u64 p12 = pack2(p1, p1);
        a1[0] = fma2(va.x, p12, a1[0]); a1[1] = fma2(va.y, p12, a1[1]);
        a1[2] = fma2(vb.x, p12, a1[2]); a1[3] = fma2(vb.y, p12, a1[3]);
        a1[4] = fma2(vc.x, p12, a1[4]); a1[5] = fma2(vc.y, p12, a1[5]);
        a1[6] = fma2(vd.x, p12, a1[6]); a1[7] = fma2(vd.y, p12, a1[7]);
    }

    size_t base = ((size_t)b*Cn + h*16)*Ln;
    float inv0 = 1.f/den0, inv1 = 1.f/den1;
    #pragma unroll
    for (int i = 0; i < 8; i++){
        float z0, z1, y0, y1;
        unpack2(a0[i], z0, z1);
        unpack2(a1[i], y0, y1);
        g_scr[base + (size_t)(2*i  )*Ln + r0] = z0*inv0;
        g_scr[base + (size_t)(2*i+1)*Ln + r0] = z1*inv0;
        g_scr[base + (size_t)(2*i  )*Ln + r1] = y0*inv1;
        g_scr[base + (size_t)(2*i+1)*Ln + r1] = y1*inv1;
    }
}

// ---------------- host launcher ----------------
extern "C" void kernel_launch(void* const* d_in, const int* in_sizes, int n_in,
                              void* d_out, int out_size){
    (void)in_sizes; (void)n_in; (void)out_size;
    const float* x    = (const float*)d_in[0];
    const float* mask = (const float*)d_in[1];
    const float* dw_w = (const float*)d_in[2];
    const float* dw_b = (const float*)d_in[3];
    const float* pw_w = (const float*)d_in[4];
    const float* pw_b = (const float*)d_in[5];
    const float* wq   = (const float*)d_in[6];
    const float* bq   = (const float*)d_in[7];
    const float* wk   = (const float*)d_in[8];
    const float* bk   = (const float*)d_in[9];
    const float* wv   = (const float*)d_in[10];
    const float* bv   = (const float*)d_in[11];
    const float* wo   = (const float*)d_in[12];
    const float* bo   = (const float*)d_in[13];
    const float* fc_w = (const float*)d_in[14];
    const float* fc_b = (const float*)d_in[15];
    const float* ln_g = (const float*)d_in[16];
    const float* ln_b = (const float*)d_in[17];
    float* outp = (float*)d_out;

    float *bufA, *bufB, *scr, *pA, *pB, *wt, *bqs;
    cudaGetSymbolAddress((void**)&bufA, g_bufA);
    cudaGetSymbolAddress((void**)&bufB, g_bufB);
    cudaGetSymbolAddress((void**)&scr,  g_scr);
    cudaGetSymbolAddress((void**)&pA,   g_partA);
    cudaGetSymbolAddress((void**)&pB,   g_partB);
    cudaGetSymbolAddress((void**)&wt,   g_wt);
    cudaGetSymbolAddress((void**)&bqs,  g_bqs);

    const int CONV_SMEM = CONV_SMEM_F * 4;
    const int MM_SMEM   = MM_SMEM_F * 4;
    const int ATTN_SMEM = ATTN_SMEM_F * 4;
    cudaFuncSetAttribute(k_conv, cudaFuncAttributeMaxDynamicSharedMemorySize, CONV_SMEM);
    cudaFuncSetAttribute(k_attn, cudaFuncAttributeMaxDynamicSharedMemorySize, ATTN_SMEM);

    // stage 0: weight transposes + ln pack
    k_prep<<<(9*Cn*Cn + 255)/256, 256>>>(pw_w, wq, wk, wv, wo, fc_w, bq, ln_g, ln_b);

    // stage 1: x + pos, LN partials -> pA
    k_pos<<<dim3(Bn, 50), 256>>>(x);

    // stage 2: 4 fused conv layers (ping-pong buffers AND ping-pong partials)
    float* cin  = bufA;
    float* cout = bufB;
    const float* pin = pA;
    float* pout = pB;
    int nparts = 50;
    for (int i = 0; i < 4; i++){
        k_conv<<<dim3(Bn, NLT), 128, CONV_SMEM>>>(cin, cout,
            wt + i*Cn*Cn, dw_w + i*Cn*Kn, dw_b + i*Cn, pw_b + i*Cn,
            pin, pout, nparts);
        float* t = cin; cin = cout; cout = t;
        float* tp = (float*)pin; pin = pout; pout = tp;
        nparts = NLT;
    }
    // cin = residual after 4 conv layers; stats partials in pin (nparts=7)

    // stage 3: attention
    k_qkv<<<dim3(Bn, NLT, 3), 128, MM_SMEM>>>(cin, bqs, bk, bv, pin, nparts);
    k_attn<<<Bn*Hn, 224, ATTN_SMEM>>>(mask);
    // o-proj: out = resid + W@scr ; stats -> pout
    k_mm<false,false,true><<<dim3(Bn, NLT), 128, MM_SMEM>>>(scr, cin, cout,
        wt + 7*Cn*Cn, bo, nullptr, pout, 0);

    // stage 4: FC + relu + residual -> final output (stats from pout)
    k_mm<true,true,false><<<dim3(Bn, NLT), 128, MM_SMEM>>>(cout, cout, outp,
        wt + 8*Cn*Cn, fc_b, pout, nullptr, NLT);
}